// round 10
// baseline (speedup 1.0000x reference)
#include <cuda_runtime.h>
#include <cstdint>

// ---------------- problem constants ----------------
#define BATCH 8192
#define KTOT  4096
#define OUTF  4096
#define SR    256

// ---------------- tile config ----------------
#define TM 128
#define TN 128
#define KC 32                  // K floats per pipeline stage
#define NSTG 5
#define NCHUNK (KTOT / KC)     // 128
#define PITCH 36               // floats per smem row (32 data + 4 pad)
#define XFLOATS (TM * PITCH)   // 4608 floats per x tile
#define STAGEF  (2 * XFLOATS)  // 9216 floats per stage (x + w)
#define STAGEB  (STAGEF * 4)   // 36864 bytes
#define SMEM_BYTES (NSTG * STAGEB)   // 184320
#define CPITCH 132             // floats per row of C staging

#define NTHREADS 512           // 16 warps: warp grid 4(M) x 4(N), warp tile 32x32

// Truncation-bias correction: feeding raw fp32 bits to tf32 MMA truncates each
// operand's mantissa to 10 bits (round-toward-zero). E[relative loss] per
// operand = 2^-11 * E[1/m] (m log-uniform in [1,2)) = 4.883e-4 * 0.7213
// = 3.522e-4; two operands -> dot product scaled by (1 - 7.044e-4).
#define TRUNC_FIX 1.0007047f

// ---------------- helpers ----------------
__device__ __forceinline__ uint32_t smem_u32(const void* p) {
    uint32_t a;
    asm("{ .reg .u64 t; cvta.to.shared.u64 t, %1; cvt.u32.u64 %0, t; }"
        : "=r"(a) : "l"(p));
    return a;
}

__device__ __forceinline__ void cp_async16(uint32_t dst, const void* src) {
    asm volatile("cp.async.cg.shared.global [%0], [%1], 16;"
                 :: "r"(dst), "l"(src) : "memory");
}

__device__ __forceinline__ void mma_tf32(float c[4],
                                         uint32_t a0, uint32_t a1,
                                         uint32_t a2, uint32_t a3,
                                         uint32_t b0, uint32_t b1) {
    asm volatile(
        "mma.sync.aligned.m16n8k8.row.col.f32.tf32.tf32.f32 "
        "{%0,%1,%2,%3}, {%4,%5,%6,%7}, {%8,%9}, {%0,%1,%2,%3};"
        : "+f"(c[0]), "+f"(c[1]), "+f"(c[2]), "+f"(c[3])
        : "r"(a0), "r"(a1), "r"(a2), "r"(a3), "r"(b0), "r"(b1));
}

// ---------------- kernel ----------------
__global__ void __launch_bounds__(NTHREADS, 1)
swfc_mma_kernel(const float* __restrict__ x, const float* __restrict__ w,
                const float* __restrict__ bias, float* __restrict__ out)
{
    extern __shared__ float smf[];
    const uint32_t* smu = reinterpret_cast<const uint32_t*>(smf);
    const int tid  = threadIdx.x;
    const int wid  = tid >> 5;
    const int lane = tid & 31;
    const int gid  = lane >> 2;     // 0..7  (mma group row)
    const int t4   = lane & 3;      // 0..3  (mma thread-in-group)
    const int wm   = wid >> 2;      // warp M index (0..3)  -> rows wm*32
    const int wn   = wid & 3;       // warp N index (0..3)  -> cols wn*32
    const int m0   = blockIdx.x * TM;
    const int n0   = blockIdx.y * TN;

    const uint32_t smem0 = smem_u32(smf);

    // Per-thread fragment base offsets (floats) into a stage tile.
    int aoff[2], boff[4];
    #pragma unroll
    for (int mt = 0; mt < 2; mt++)
        aoff[mt] = (wm * 32 + mt * 16 + gid) * PITCH + t4;
    #pragma unroll
    for (int nt = 0; nt < 4; nt++)
        boff[nt] = (wn * 32 + nt * 8 + gid) * PITCH + t4;

    float c[2][4][4];
    #pragma unroll
    for (int mt = 0; mt < 2; mt++)
        #pragma unroll
        for (int nt = 0; nt < 4; nt++)
            #pragma unroll
            for (int r = 0; r < 4; r++)
                c[mt][nt][r] = 0.0f;

    // ---- async load of one K-chunk into a stage slot ----
    // 128 rows x 8 segments of 16B for each of x and w -> 2048 segs total,
    // 4 per thread at 512 threads (2 x, 2 w).
    auto load_chunk = [&](int ck, int slot) {
        const int k0 = ck * KC;
        const uint32_t xbase = smem0 + slot * STAGEB;
        const uint32_t wbase = xbase + XFLOATS * 4;
        #pragma unroll
        for (int j = 0; j < 2; j++) {
            const int lin = j * NTHREADS + tid;  // 0..1023
            const int row = lin >> 3;
            const int seg = lin & 7;             // 16B segment within 128B row
            cp_async16(xbase + (uint32_t)(row * PITCH + seg * 4) * 4,
                       x + (size_t)(m0 + row) * KTOT + k0 + seg * 4);
            cp_async16(wbase + (uint32_t)(row * PITCH + seg * 4) * 4,
                       w + (size_t)(n0 + row) * KTOT + k0 + seg * 4);
        }
    };

    // ---- prologue: fill NSTG-1 stages ----
    #pragma unroll
    for (int s = 0; s < NSTG - 1; s++) {
        load_chunk(s, s);
        asm volatile("cp.async.commit_group;" ::: "memory");
    }

    // ---- mainloop ----
    #pragma unroll 1
    for (int i = 0; i < NCHUNK; i++) {
        asm volatile("cp.async.wait_group 3;" ::: "memory");  // chunk i resident
        __syncthreads();   // everyone done with old slot; chunk i visible

        const int nx = i + NSTG - 1;
        if (nx < NCHUNK) {
            load_chunk(nx, nx % NSTG);
            asm volatile("cp.async.commit_group;" ::: "memory");
        }

        const uint32_t* xs = smu + (i % NSTG) * STAGEF;
        const uint32_t* ws = xs + XFLOATS;

        #pragma unroll
        for (int kc = 0; kc < 4; kc++) {
            uint32_t A[2][4];
            #pragma unroll
            for (int mt = 0; mt < 2; mt++) {
                const int ib = aoff[mt] + kc * 8;
                A[mt][0] = xs[ib];
                A[mt][1] = xs[ib + 8 * PITCH];
                A[mt][2] = xs[ib + 4];
                A[mt][3] = xs[ib + 8 * PITCH + 4];
            }
            uint32_t B[4][2];
            #pragma unroll
            for (int nt = 0; nt < 4; nt++) {
                const int ib = boff[nt] + kc * 8;
                B[nt][0] = ws[ib];
                B[nt][1] = ws[ib + 4];
            }
            #pragma unroll
            for (int mt = 0; mt < 2; mt++)
                #pragma unroll
                for (int nt = 0; nt < 4; nt++)
                    mma_tf32(c[mt][nt],
                             A[mt][0], A[mt][1], A[mt][2], A[mt][3],
                             B[nt][0], B[nt][1]);
        }
    }

    // ---- epilogue stage 1: accums -> smem C (pitch CPITCH) ----
    __syncthreads();   // all stage reads done; reuse pipeline smem
    float* C = smf;
    #pragma unroll
    for (int mt = 0; mt < 2; mt++) {
        #pragma unroll
        for (int nt = 0; nt < 4; nt++) {
            const int r0 = wm * 32 + mt * 16 + gid;
            const int c0 = wn * 32 + nt * 8 + 2 * t4;
            *reinterpret_cast<float2*>(&C[r0 * CPITCH + c0]) =
                make_float2(c[mt][nt][0], c[mt][nt][1]);
            *reinterpret_cast<float2*>(&C[(r0 + 8) * CPITCH + c0]) =
                make_float2(c[mt][nt][2], c[mt][nt][3]);
        }
    }
    __syncthreads();

    // ---- epilogue stage 2: 16x column-replication with bias ----
    // Out cols for this CTA: n0 + 4*c4 + {0..3} + 256*rep, rep = 0..15.
    const int c4    = tid & 31;      // float4 column within the 128-col tile
    const int rbase = tid >> 5;      // 0..15
    const float4* bias4 = reinterpret_cast<const float4*>(bias);
    float4 bv[16];
    #pragma unroll
    for (int r = 0; r < 16; r++)
        bv[r] = bias4[r * 64 + (n0 >> 2) + c4];

    #pragma unroll 1
    for (int row = rbase; row < TM; row += 16) {
        float4 v = *reinterpret_cast<const float4*>(&C[row * CPITCH + c4 * 4]);
        v.x *= TRUNC_FIX; v.y *= TRUNC_FIX; v.z *= TRUNC_FIX; v.w *= TRUNC_FIX;
        float* orow = out + (size_t)(m0 + row) * OUTF + n0 + c4 * 4;
        #pragma unroll
        for (int r = 0; r < 16; r++) {
            float4 o;
            o.x = v.x + bv[r].x;
            o.y = v.y + bv[r].y;
            o.z = v.z + bv[r].z;
            o.w = v.w + bv[r].w;
            *reinterpret_cast<float4*>(&orow[r * 256]) = o;
        }
    }
}

// ---------------- host side ----------------
extern "C" void kernel_launch(void* const* d_in, const int* in_sizes, int n_in,
                              void* d_out, int out_size) {
    const float* x    = (const float*)d_in[0];   // [8192, 4096]
    const float* w    = (const float*)d_in[1];   // [256, 4096]
    const float* bias = (const float*)d_in[2];   // [4096]
    float* out        = (float*)d_out;           // [8192, 4096]

    static bool attr_set = false;
    if (!attr_set) {
        cudaFuncSetAttribute(swfc_mma_kernel,
                             cudaFuncAttributeMaxDynamicSharedMemorySize,
                             SMEM_BYTES);
        attr_set = true;
    }

    swfc_mma_kernel<<<dim3(BATCH / TM, SR / TN), NTHREADS, SMEM_BYTES>>>(x, w, bias, out);
}

// round 11
// speedup vs baseline: 1.1062x; 1.1062x over previous
#include <cuda_runtime.h>
#include <cstdint>

// ---------------- problem constants ----------------
#define BATCH 8192
#define KTOT  4096
#define OUTF  4096
#define SR    256

// ---------------- tile config ----------------
#define TM 128
#define TN 128
#define KC 64                  // K floats per pipeline stage (2x R8: fewer barriers)
#define NSTG 3
#define NCHUNK (KTOT / KC)     // 64
#define PITCH 68               // floats per smem row (64 data + 4 pad); 68 mod 32 = 4
#define XFLOATS (TM * PITCH)   // 8704 floats per x tile
#define STAGEF  (2 * XFLOATS)  // 17408 floats per stage (x + w)
#define STAGEB  (STAGEF * 4)   // 69632 bytes
#define SMEM_BYTES (NSTG * STAGEB)   // 208896
#define CPITCH 132             // floats per row of C staging

#define NTHREADS 256           // 8 warps: warp grid 2(M) x 4(N), warp tile 64x32

// Truncation-bias correction: feeding raw fp32 bits to tf32 MMA truncates each
// operand's mantissa to 10 bits (round-toward-zero). E[relative loss] per
// operand = 2^-11 * E[1/m] (m log-uniform in [1,2)) = 3.522e-4; two operands
// -> dot product scaled by (1 - 7.044e-4). Undo in epilogue.
#define TRUNC_FIX 1.0007047f

// ---------------- helpers ----------------
__device__ __forceinline__ uint32_t smem_u32(const void* p) {
    uint32_t a;
    asm("{ .reg .u64 t; cvta.to.shared.u64 t, %1; cvt.u32.u64 %0, t; }"
        : "=r"(a) : "l"(p));
    return a;
}

__device__ __forceinline__ void cp_async16(uint32_t dst, const void* src) {
    asm volatile("cp.async.cg.shared.global [%0], [%1], 16;"
                 :: "r"(dst), "l"(src) : "memory");
}

__device__ __forceinline__ void mma_tf32(float c[4],
                                         uint32_t a0, uint32_t a1,
                                         uint32_t a2, uint32_t a3,
                                         uint32_t b0, uint32_t b1) {
    asm volatile(
        "mma.sync.aligned.m16n8k8.row.col.f32.tf32.tf32.f32 "
        "{%0,%1,%2,%3}, {%4,%5,%6,%7}, {%8,%9}, {%0,%1,%2,%3};"
        : "+f"(c[0]), "+f"(c[1]), "+f"(c[2]), "+f"(c[3])
        : "r"(a0), "r"(a1), "r"(a2), "r"(a3), "r"(b0), "r"(b1));
}

// ---------------- kernel ----------------
__global__ void __launch_bounds__(NTHREADS, 1)
swfc_mma_kernel(const float* __restrict__ x, const float* __restrict__ w,
                const float* __restrict__ bias, float* __restrict__ out)
{
    extern __shared__ float smf[];
    const uint32_t* smu = reinterpret_cast<const uint32_t*>(smf);
    const int tid  = threadIdx.x;
    const int wid  = tid >> 5;
    const int lane = tid & 31;
    const int gid  = lane >> 2;     // 0..7  (mma group row)
    const int t4   = lane & 3;      // 0..3  (mma thread-in-group)
    const int wm   = wid >> 2;      // warp M index (0..1)  -> rows wm*64
    const int wn   = wid & 3;       // warp N index (0..3)  -> cols wn*32
    const int m0   = blockIdx.x * TM;
    const int n0   = blockIdx.y * TN;

    const uint32_t smem0 = smem_u32(smf);

    // Per-thread fragment base offsets (floats) into a stage tile.
    int aoff[4], boff[4];
    #pragma unroll
    for (int mt = 0; mt < 4; mt++)
        aoff[mt] = (wm * 64 + mt * 16 + gid) * PITCH + t4;
    #pragma unroll
    for (int nt = 0; nt < 4; nt++)
        boff[nt] = (wn * 32 + nt * 8 + gid) * PITCH + t4;

    float c[4][4][4];
    #pragma unroll
    for (int mt = 0; mt < 4; mt++)
        #pragma unroll
        for (int nt = 0; nt < 4; nt++)
            #pragma unroll
            for (int r = 0; r < 4; r++)
                c[mt][nt][r] = 0.0f;

    // ---- async load of one K-chunk (64 floats deep) into a stage slot ----
    // 128 rows x 16 segments of 16B for each of x and w -> 4096 segs total,
    // 16 per thread at 256 threads (8 x, 8 w).
    auto load_chunk = [&](int ck, int slot) {
        const int k0 = ck * KC;
        const uint32_t xbase = smem0 + slot * STAGEB;
        const uint32_t wbase = xbase + XFLOATS * 4;
        #pragma unroll
        for (int j = 0; j < 8; j++) {
            const int lin = j * NTHREADS + tid;  // 0..2047
            const int row = lin >> 4;
            const int seg = lin & 15;            // 16B segment within 256B row
            cp_async16(xbase + (uint32_t)(row * PITCH + seg * 4) * 4,
                       x + (size_t)(m0 + row) * KTOT + k0 + seg * 4);
            cp_async16(wbase + (uint32_t)(row * PITCH + seg * 4) * 4,
                       w + (size_t)(n0 + row) * KTOT + k0 + seg * 4);
        }
    };

    // ---- prologue: fill NSTG-1 = 2 stages ----
    #pragma unroll
    for (int s = 0; s < NSTG - 1; s++) {
        load_chunk(s, s);
        asm volatile("cp.async.commit_group;" ::: "memory");
    }

    // ---- mainloop ----
    #pragma unroll 1
    for (int i = 0; i < NCHUNK; i++) {
        asm volatile("cp.async.wait_group 1;" ::: "memory");  // chunk i resident
        __syncthreads();   // everyone done with old slot; chunk i visible

        const int nx = i + NSTG - 1;
        if (nx < NCHUNK) {
            load_chunk(nx, nx % NSTG);
            asm volatile("cp.async.commit_group;" ::: "memory");
        }

        const uint32_t* xs = smu + (i % NSTG) * STAGEF;
        const uint32_t* ws = xs + XFLOATS;

        // Software-pipelined over 8 kc-steps: fetch kc+1 fragments while
        // issuing kc MMAs so LDS latency overlaps tensor work.
        uint32_t A[4][4], B[4][2];
        #pragma unroll
        for (int mt = 0; mt < 4; mt++) {
            const int ib = aoff[mt];
            A[mt][0] = xs[ib];
            A[mt][1] = xs[ib + 8 * PITCH];
            A[mt][2] = xs[ib + 4];
            A[mt][3] = xs[ib + 8 * PITCH + 4];
        }
        #pragma unroll
        for (int nt = 0; nt < 4; nt++) {
            const int ib = boff[nt];
            B[nt][0] = ws[ib];
            B[nt][1] = ws[ib + 4];
        }

        #pragma unroll
        for (int kc = 0; kc < 8; kc++) {
            uint32_t An[4][4], Bn[4][2];
            if (kc < 7) {
                const int kb = (kc + 1) * 8;
                #pragma unroll
                for (int mt = 0; mt < 4; mt++) {
                    const int ib = aoff[mt] + kb;
                    An[mt][0] = xs[ib];
                    An[mt][1] = xs[ib + 8 * PITCH];
                    An[mt][2] = xs[ib + 4];
                    An[mt][3] = xs[ib + 8 * PITCH + 4];
                }
                #pragma unroll
                for (int nt = 0; nt < 4; nt++) {
                    const int ib = boff[nt] + kb;
                    Bn[nt][0] = ws[ib];
                    Bn[nt][1] = ws[ib + 4];
                }
            }
            #pragma unroll
            for (int mt = 0; mt < 4; mt++)
                #pragma unroll
                for (int nt = 0; nt < 4; nt++)
                    mma_tf32(c[mt][nt],
                             A[mt][0], A[mt][1], A[mt][2], A[mt][3],
                             B[nt][0], B[nt][1]);
            if (kc < 7) {
                #pragma unroll
                for (int mt = 0; mt < 4; mt++) {
                    A[mt][0] = An[mt][0]; A[mt][1] = An[mt][1];
                    A[mt][2] = An[mt][2]; A[mt][3] = An[mt][3];
                }
                #pragma unroll
                for (int nt = 0; nt < 4; nt++) {
                    B[nt][0] = Bn[nt][0]; B[nt][1] = Bn[nt][1];
                }
            }
        }
    }

    // ---- epilogue stage 1: accums -> smem C (pitch CPITCH) ----
    __syncthreads();   // all stage reads done; reuse pipeline smem
    float* C = smf;
    #pragma unroll
    for (int mt = 0; mt < 4; mt++) {
        #pragma unroll
        for (int nt = 0; nt < 4; nt++) {
            const int r0 = wm * 64 + mt * 16 + gid;
            const int c0 = wn * 32 + nt * 8 + 2 * t4;
            *reinterpret_cast<float2*>(&C[r0 * CPITCH + c0]) =
                make_float2(c[mt][nt][0], c[mt][nt][1]);
            *reinterpret_cast<float2*>(&C[(r0 + 8) * CPITCH + c0]) =
                make_float2(c[mt][nt][2], c[mt][nt][3]);
        }
    }
    __syncthreads();

    // ---- epilogue stage 2: 16x column-replication with bias ----
    // Out cols for this CTA: n0 + 4*c4 + {0..3} + 256*rep, rep = 0..15.
    const int c4    = tid & 31;      // float4 column within the 128-col tile
    const int rbase = tid >> 5;      // 0..7
    const float4* bias4 = reinterpret_cast<const float4*>(bias);
    float4 bv[16];
    #pragma unroll
    for (int r = 0; r < 16; r++)
        bv[r] = bias4[r * 64 + (n0 >> 2) + c4];

    #pragma unroll 1
    for (int row = rbase; row < TM; row += 8) {
        float4 v = *reinterpret_cast<const float4*>(&C[row * CPITCH + c4 * 4]);
        v.x *= TRUNC_FIX; v.y *= TRUNC_FIX; v.z *= TRUNC_FIX; v.w *= TRUNC_FIX;
        float* orow = out + (size_t)(m0 + row) * OUTF + n0 + c4 * 4;
        #pragma unroll
        for (int r = 0; r < 16; r++) {
            float4 o;
            o.x = v.x + bv[r].x;
            o.y = v.y + bv[r].y;
            o.z = v.z + bv[r].z;
            o.w = v.w + bv[r].w;
            *reinterpret_cast<float4*>(&orow[r * 256]) = o;
        }
    }
}

// ---------------- host side ----------------
extern "C" void kernel_launch(void* const* d_in, const int* in_sizes, int n_in,
                              void* d_out, int out_size) {
    const float* x    = (const float*)d_in[0];   // [8192, 4096]
    const float* w    = (const float*)d_in[1];   // [256, 4096]
    const float* bias = (const float*)d_in[2];   // [4096]
    float* out        = (float*)d_out;           // [8192, 4096]

    static bool attr_set = false;
    if (!attr_set) {
        cudaFuncSetAttribute(swfc_mma_kernel,
                             cudaFuncAttributeMaxDynamicSharedMemorySize,
                             SMEM_BYTES);
        attr_set = true;
    }

    swfc_mma_kernel<<<dim3(BATCH / TM, SR / TN), NTHREADS, SMEM_BYTES>>>(x, w, bias, out);
}

// round 13
// speedup vs baseline: 1.1408x; 1.0312x over previous
#include <cuda_runtime.h>
#include <cstdint>

// ---------------- problem constants ----------------
#define BATCH 8192
#define KTOT  4096
#define OUTF  4096
#define SR    256

// ---------------- tile config ----------------
#define TM 128
#define TN 128
#define KC 64                  // K floats per pipeline stage
#define NSTG 3
#define NCHUNK (KTOT / KC)     // 64
#define PITCH 68               // floats per smem row; 68*4=272B ≡ 16B (mod 128) -> LDSM conflict-free
#define XFLOATS (TM * PITCH)   // 8704 floats per x tile
#define STAGEF  (2 * XFLOATS)  // 17408 floats per stage (x + w)
#define STAGEB  (STAGEF * 4)   // 69632 bytes
#define SMEM_BYTES (NSTG * STAGEB)   // 208896
#define CPITCH 132             // floats per row of C staging

#define NTHREADS 256           // 8 warps: warp grid 2(M) x 4(N), warp tile 64x32

// Truncation-bias correction: feeding raw fp32 bits to tf32 MMA truncates each
// operand's mantissa to 10 bits (round-toward-zero). E[relative loss] per
// operand = 2^-11 * E[1/m] (m log-uniform in [1,2)) = 3.522e-4; two operands
// -> dot product scaled by (1 - 7.044e-4). Undo in epilogue.
#define TRUNC_FIX 1.0007047f

// ---------------- helpers ----------------
__device__ __forceinline__ uint32_t smem_u32(const void* p) {
    uint32_t a;
    asm("{ .reg .u64 t; cvta.to.shared.u64 t, %1; cvt.u32.u64 %0, t; }"
        : "=r"(a) : "l"(p));
    return a;
}

__device__ __forceinline__ void cp_async16(uint32_t dst, const void* src) {
    asm volatile("cp.async.cg.shared.global [%0], [%1], 16;"
                 :: "r"(dst), "l"(src) : "memory");
}

__device__ __forceinline__ void ldsm_x4(uint32_t r[4], uint32_t addr) {
    asm volatile("ldmatrix.sync.aligned.m8n8.x4.shared.b16 {%0,%1,%2,%3}, [%4];"
                 : "=r"(r[0]), "=r"(r[1]), "=r"(r[2]), "=r"(r[3]) : "r"(addr));
}

__device__ __forceinline__ void ldsm_x2(uint32_t r[2], uint32_t addr) {
    asm volatile("ldmatrix.sync.aligned.m8n8.x2.shared.b16 {%0,%1}, [%2];"
                 : "=r"(r[0]), "=r"(r[1]) : "r"(addr));
}

__device__ __forceinline__ void mma_tf32(float c[4],
                                         uint32_t a0, uint32_t a1,
                                         uint32_t a2, uint32_t a3,
                                         uint32_t b0, uint32_t b1) {
    asm volatile(
        "mma.sync.aligned.m16n8k8.row.col.f32.tf32.tf32.f32 "
        "{%0,%1,%2,%3}, {%4,%5,%6,%7}, {%8,%9}, {%0,%1,%2,%3};"
        : "+f"(c[0]), "+f"(c[1]), "+f"(c[2]), "+f"(c[3])
        : "r"(a0), "r"(a1), "r"(a2), "r"(a3), "r"(b0), "r"(b1));
}

// ---------------- kernel ----------------
__global__ void __launch_bounds__(NTHREADS, 1)
swfc_mma_kernel(const float* __restrict__ x, const float* __restrict__ w,
                const float* __restrict__ bias, float* __restrict__ out)
{
    extern __shared__ float smf[];
    const int tid  = threadIdx.x;
    const int wid  = tid >> 5;
    const int lane = tid & 31;
    const int gid  = lane >> 2;     // 0..7  (mma group row)
    const int t4   = lane & 3;      // 0..3  (mma thread-in-group)
    const int wm   = wid >> 2;      // warp M index (0..1)  -> rows wm*64
    const int wn   = wid & 3;       // warp N index (0..3)  -> cols wn*32
    const int m0   = blockIdx.x * TM;
    const int n0   = blockIdx.y * TN;

    const uint32_t smem0 = smem_u32(smf);

    // ldmatrix per-lane row-pointer offsets (bytes within a stage tile, kc=0).
    // A (x4): lanes 0-7 -> mat0 rows (row base, k cols 0-3)
    //         lanes 8-15 -> mat1 (row+8, k 0-3)
    //         lanes 16-23 -> mat2 (row, k 4-7), 24-31 -> mat3 (row+8, k 4-7)
    // B (x2): lanes 0-7 -> mat0 (n rows, k 0-3), 8-15 -> mat1 (n rows, k 4-7)
    uint32_t aoffb[4], boffb[4];
    {
        const int arow_l = ((lane >> 3) & 1) * 8 + (lane & 7);
        const int acol_l = ((lane >> 4) & 1) * 4;
        #pragma unroll
        for (int mt = 0; mt < 4; mt++)
            aoffb[mt] = (uint32_t)(((wm * 64 + mt * 16 + arow_l) * PITCH + acol_l) * 4);
        const int brow_l = lane & 7;
        const int bcol_l = ((lane >> 3) & 1) * 4;
        #pragma unroll
        for (int nt = 0; nt < 4; nt++)
            boffb[nt] = (uint32_t)(((wn * 32 + nt * 8 + brow_l) * PITCH + bcol_l) * 4
                                   + XFLOATS * 4);
    }

    float c[4][4][4];
    #pragma unroll
    for (int mt = 0; mt < 4; mt++)
        #pragma unroll
        for (int nt = 0; nt < 4; nt++)
            #pragma unroll
            for (int r = 0; r < 4; r++)
                c[mt][nt][r] = 0.0f;

    // ---- async load of one K-chunk (64 floats deep) into a stage slot ----
    auto load_chunk = [&](int ck, int slot) {
        const int k0 = ck * KC;
        const uint32_t xbase = smem0 + slot * STAGEB;
        const uint32_t wbase = xbase + XFLOATS * 4;
        #pragma unroll
        for (int j = 0; j < 8; j++) {
            const int lin = j * NTHREADS + tid;  // 0..2047
            const int row = lin >> 4;
            const int seg = lin & 15;            // 16B segment within 256B row
            cp_async16(xbase + (uint32_t)(row * PITCH + seg * 4) * 4,
                       x + (size_t)(m0 + row) * KTOT + k0 + seg * 4);
            cp_async16(wbase + (uint32_t)(row * PITCH + seg * 4) * 4,
                       w + (size_t)(n0 + row) * KTOT + k0 + seg * 4);
        }
    };

    // ---- prologue: fill NSTG-1 = 2 stages ----
    #pragma unroll
    for (int s = 0; s < NSTG - 1; s++) {
        load_chunk(s, s);
        asm volatile("cp.async.commit_group;" ::: "memory");
    }

    // ---- mainloop ----
    #pragma unroll 1
    for (int i = 0; i < NCHUNK; i++) {
        asm volatile("cp.async.wait_group 1;" ::: "memory");  // chunk i resident
        __syncthreads();   // everyone done with old slot; chunk i visible

        const int nx = i + NSTG - 1;
        if (nx < NCHUNK) {
            load_chunk(nx, nx % NSTG);
            asm volatile("cp.async.commit_group;" ::: "memory");
        }

        const uint32_t stg = smem0 + (i % NSTG) * STAGEB;

        // Software-pipelined over 8 kc-steps: ldmatrix kc+1 while MMA kc.
        uint32_t A[4][4], B[4][2];
        #pragma unroll
        for (int mt = 0; mt < 4; mt++) ldsm_x4(A[mt], stg + aoffb[mt]);
        #pragma unroll
        for (int nt = 0; nt < 4; nt++) ldsm_x2(B[nt], stg + boffb[nt]);

        #pragma unroll
        for (int kc = 0; kc < 8; kc++) {
            uint32_t An[4][4], Bn[4][2];
            if (kc < 7) {
                const uint32_t kb = (uint32_t)(kc + 1) * 32;  // 8 floats per kc
                #pragma unroll
                for (int mt = 0; mt < 4; mt++) ldsm_x4(An[mt], stg + aoffb[mt] + kb);
                #pragma unroll
                for (int nt = 0; nt < 4; nt++) ldsm_x2(Bn[nt], stg + boffb[nt] + kb);
            }
            #pragma unroll
            for (int mt = 0; mt < 4; mt++)
                #pragma unroll
                for (int nt = 0; nt < 4; nt++)
                    mma_tf32(c[mt][nt],
                             A[mt][0], A[mt][1], A[mt][2], A[mt][3],
                             B[nt][0], B[nt][1]);
            if (kc < 7) {
                #pragma unroll
                for (int mt = 0; mt < 4; mt++) {
                    A[mt][0] = An[mt][0]; A[mt][1] = An[mt][1];
                    A[mt][2] = An[mt][2]; A[mt][3] = An[mt][3];
                }
                #pragma unroll
                for (int nt = 0; nt < 4; nt++) {
                    B[nt][0] = Bn[nt][0]; B[nt][1] = Bn[nt][1];
                }
            }
        }
    }

    // ---- epilogue stage 1: accums -> smem C (pitch CPITCH) ----
    __syncthreads();   // all stage reads done; reuse pipeline smem
    float* C = smf;
    #pragma unroll
    for (int mt = 0; mt < 4; mt++) {
        #pragma unroll
        for (int nt = 0; nt < 4; nt++) {
            const int r0 = wm * 64 + mt * 16 + gid;
            const int c0 = wn * 32 + nt * 8 + 2 * t4;
            *reinterpret_cast<float2*>(&C[r0 * CPITCH + c0]) =
                make_float2(c[mt][nt][0], c[mt][nt][1]);
            *reinterpret_cast<float2*>(&C[(r0 + 8) * CPITCH + c0]) =
                make_float2(c[mt][nt][2], c[mt][nt][3]);
        }
    }
    __syncthreads();

    // ---- epilogue stage 2: 16x column-replication with bias ----
    // Out cols for this CTA: n0 + 4*c4 + {0..3} + 256*rep, rep = 0..15.
    const int c4    = tid & 31;      // float4 column within the 128-col tile
    const int rbase = tid >> 5;      // 0..7
    const float4* bias4 = reinterpret_cast<const float4*>(bias);
    float4 bv[16];
    #pragma unroll
    for (int r = 0; r < 16; r++)
        bv[r] = bias4[r * 64 + (n0 >> 2) + c4];

    #pragma unroll 1
    for (int row = rbase; row < TM; row += 8) {
        float4 v = *reinterpret_cast<const float4*>(&C[row * CPITCH + c4 * 4]);
        v.x *= TRUNC_FIX; v.y *= TRUNC_FIX; v.z *= TRUNC_FIX; v.w *= TRUNC_FIX;
        float* orow = out + (size_t)(m0 + row) * OUTF + n0 + c4 * 4;
        #pragma unroll
        for (int r = 0; r < 16; r++) {
            float4 o;
            o.x = v.x + bv[r].x;
            o.y = v.y + bv[r].y;
            o.z = v.z + bv[r].z;
            o.w = v.w + bv[r].w;
            *reinterpret_cast<float4*>(&orow[r * 256]) = o;
        }
    }
}

// ---------------- host side ----------------
extern "C" void kernel_launch(void* const* d_in, const int* in_sizes, int n_in,
                              void* d_out, int out_size) {
    const float* x    = (const float*)d_in[0];   // [8192, 4096]
    const float* w    = (const float*)d_in[1];   // [256, 4096]
    const float* bias = (const float*)d_in[2];   // [4096]
    float* out        = (float*)d_out;           // [8192, 4096]

    static bool attr_set = false;
    if (!attr_set) {
        cudaFuncSetAttribute(swfc_mma_kernel,
                             cudaFuncAttributeMaxDynamicSharedMemorySize,
                             SMEM_BYTES);
        attr_set = true;
    }

    swfc_mma_kernel<<<dim3(BATCH / TM, SR / TN), NTHREADS, SMEM_BYTES>>>(x, w, bias, out);
}

// round 14
// speedup vs baseline: 1.2234x; 1.0724x over previous
#include <cuda_runtime.h>
#include <cstdint>

// ---------------- problem constants ----------------
#define BATCH 8192
#define KTOT  4096
#define OUTF  4096
#define SR    256

// ---------------- tile config ----------------
// K-split: each CTA computes C_tile[128 x 256] over HALF of K (2048).
// Pairs of CTAs (same M-tile) combine partials through global scratch.
#define TM 128
#define TN 256                 // full shared-rows width
#define KHALF 2048
#define KC 64                  // K floats per pipeline stage
#define NSTG 2
#define NCHUNK (KHALF / KC)    // 32
#define PITCH 68               // floats per smem row; 272B = 16B (mod 128): LDSM conflict-free
#define SROWS (TM + TN)        // 384 rows per stage (x then w)
#define STAGEF (SROWS * PITCH) // 26112 floats
#define STAGEB (STAGEF * 4)    // 104448 bytes
#define SMEM_BYTES (NSTG * STAGEB)   // 208896
#define CPITCH 260             // floats per row of C staging (256 + 4 pad)

#define NTHREADS 256           // 8 warps: warp grid 2(M) x 4(N), warp tile 64x64

// Truncation-bias correction (raw fp32 bits into tf32 MMA = truncation):
// dot product scaled by (1 - 7.044e-4); undo in epilogue.
#define TRUNC_FIX 1.0007047f

// ---------------- global scratch (no allocation allowed) ----------------
// partials: [64 m-tiles][2 k-halves][128*256]
__device__ float g_scratch[64 * 2 * TM * TN];
__device__ int   g_cnt[64];
__device__ int   g_done[64];

// ---------------- helpers ----------------
__device__ __forceinline__ uint32_t smem_u32(const void* p) {
    uint32_t a;
    asm("{ .reg .u64 t; cvta.to.shared.u64 t, %1; cvt.u32.u64 %0, t; }"
        : "=r"(a) : "l"(p));
    return a;
}

__device__ __forceinline__ void cp_async16(uint32_t dst, const void* src) {
    asm volatile("cp.async.cg.shared.global [%0], [%1], 16;"
                 :: "r"(dst), "l"(src) : "memory");
}

__device__ __forceinline__ void ldsm_x4(uint32_t* r, uint32_t addr) {
    asm volatile("ldmatrix.sync.aligned.m8n8.x4.shared.b16 {%0,%1,%2,%3}, [%4];"
                 : "=r"(r[0]), "=r"(r[1]), "=r"(r[2]), "=r"(r[3]) : "r"(addr));
}

__device__ __forceinline__ void mma_tf32(float c[4],
                                         uint32_t a0, uint32_t a1,
                                         uint32_t a2, uint32_t a3,
                                         uint32_t b0, uint32_t b1) {
    asm volatile(
        "mma.sync.aligned.m16n8k8.row.col.f32.tf32.tf32.f32 "
        "{%0,%1,%2,%3}, {%4,%5,%6,%7}, {%8,%9}, {%0,%1,%2,%3};"
        : "+f"(c[0]), "+f"(c[1]), "+f"(c[2]), "+f"(c[3])
        : "r"(a0), "r"(a1), "r"(a2), "r"(a3), "r"(b0), "r"(b1));
}

// ---------------- kernel ----------------
__global__ void __launch_bounds__(NTHREADS, 1)
swfc_mma_kernel(const float* __restrict__ x, const float* __restrict__ w,
                const float* __restrict__ bias, float* __restrict__ out)
{
    extern __shared__ float smf[];
    const int tid  = threadIdx.x;
    const int wid  = tid >> 5;
    const int lane = tid & 31;
    const int gid  = lane >> 2;     // 0..7
    const int t4   = lane & 3;      // 0..3
    const int wm   = wid >> 2;      // 0..1 -> rows wm*64
    const int wn   = wid & 3;       // 0..3 -> cols wn*64
    const int mtile = blockIdx.x >> 1;
    const int khalf = blockIdx.x & 1;
    const int m0    = mtile * TM;
    const int kbase = khalf * KHALF;

    const uint32_t smem0 = smem_u32(smf);

    // ldmatrix lane offsets (bytes within a stage tile, kc=0).
    // A x4: lanes 0-7 row base k0-3 | 8-15 row+8 k0-3 | 16-23 row k4-7 | 24-31 row+8 k4-7
    uint32_t aoffb[4];
    {
        const int arow = ((lane >> 3) & 1) * 8 + (lane & 7);
        const int acol = ((lane >> 4) & 1) * 4;
        #pragma unroll
        for (int mt = 0; mt < 4; mt++)
            aoffb[mt] = (uint32_t)(((wm * 64 + mt * 16 + arow) * PITCH + acol) * 4);
    }
    // B x4: lanes 0-7 n0-7 k0-3 | 8-15 n0-7 k4-7 | 16-23 n8-15 k0-3 | 24-31 n8-15 k4-7
    uint32_t boffb[4];
    {
        const int brow = ((lane >> 4) & 1) * 8 + (lane & 7);
        const int bcol = ((lane >> 3) & 1) * 4;
        #pragma unroll
        for (int p = 0; p < 4; p++)
            boffb[p] = (uint32_t)(((TM + wn * 64 + p * 16 + brow) * PITCH + bcol) * 4);
    }

    float c[4][8][4];
    #pragma unroll
    for (int mt = 0; mt < 4; mt++)
        #pragma unroll
        for (int nt = 0; nt < 8; nt++)
            #pragma unroll
            for (int r = 0; r < 4; r++)
                c[mt][nt][r] = 0.0f;

    // ---- async load of one K-chunk: 384 rows (128 x + 256 w) x 64 floats ----
    // 384*16 = 6144 16B segs, 24 per thread.
    auto load_chunk = [&](int ck, int slot) {
        const int k0 = kbase + ck * KC;
        const uint32_t base = smem0 + slot * STAGEB;
        #pragma unroll
        for (int j = 0; j < 8; j++) {           // x: 2048 segs
            const int lin = j * NTHREADS + tid;
            const int row = lin >> 4;
            const int seg = lin & 15;
            cp_async16(base + (uint32_t)(row * PITCH + seg * 4) * 4,
                       x + (size_t)(m0 + row) * KTOT + k0 + seg * 4);
        }
        const uint32_t wb = base + (uint32_t)TM * PITCH * 4;
        #pragma unroll
        for (int j = 0; j < 16; j++) {          // w: 4096 segs
            const int lin = j * NTHREADS + tid;
            const int row = lin >> 4;
            const int seg = lin & 15;
            cp_async16(wb + (uint32_t)(row * PITCH + seg * 4) * 4,
                       w + (size_t)row * KTOT + k0 + seg * 4);
        }
    };

    // ---- prologue: load chunk 0 ----
    load_chunk(0, 0);
    asm volatile("cp.async.commit_group;" ::: "memory");

    // ---- mainloop (2-stage) ----
    #pragma unroll 1
    for (int i = 0; i < NCHUNK; i++) {
        // all warps done computing chunk i-1 before overwriting its slot
        __syncthreads();
        if (i + 1 < NCHUNK) {
            load_chunk(i + 1, (i + 1) & 1);
            asm volatile("cp.async.commit_group;" ::: "memory");
            asm volatile("cp.async.wait_group 1;" ::: "memory");  // chunk i done
        } else {
            asm volatile("cp.async.wait_group 0;" ::: "memory");
        }
        __syncthreads();

        const uint32_t stg = smem0 + (i & 1) * STAGEB;

        #pragma unroll
        for (int kc = 0; kc < 8; kc++) {
            const uint32_t kb = (uint32_t)kc * 32;   // 8 floats
            uint32_t A[4][4], B[8][2];
            #pragma unroll
            for (int mt = 0; mt < 4; mt++) ldsm_x4(&A[mt][0], stg + aoffb[mt] + kb);
            #pragma unroll
            for (int p = 0; p < 4; p++)   ldsm_x4(&B[2 * p][0], stg + boffb[p] + kb);
            #pragma unroll
            for (int mt = 0; mt < 4; mt++)
                #pragma unroll
                for (int nt = 0; nt < 8; nt++)
                    mma_tf32(c[mt][nt],
                             A[mt][0], A[mt][1], A[mt][2], A[mt][3],
                             B[nt][0], B[nt][1]);
        }
    }

    // ---- epilogue stage 1: accums -> smem C (128 x 256, pitch CPITCH) ----
    __syncthreads();
    float* C = smf;
    #pragma unroll
    for (int mt = 0; mt < 4; mt++) {
        #pragma unroll
        for (int nt = 0; nt < 8; nt++) {
            const int r0 = wm * 64 + mt * 16 + gid;
            const int c0 = wn * 64 + nt * 8 + 2 * t4;
            *reinterpret_cast<float2*>(&C[r0 * CPITCH + c0]) =
                make_float2(c[mt][nt][0], c[mt][nt][1]);
            *reinterpret_cast<float2*>(&C[(r0 + 8) * CPITCH + c0]) =
                make_float2(c[mt][nt][2], c[mt][nt][3]);
        }
    }
    __syncthreads();

    // ---- write own partial to scratch (coalesced) ----
    {
        float4* dst = reinterpret_cast<float4*>(
            g_scratch + (size_t)(mtile * 2 + khalf) * (TM * TN));
        #pragma unroll 1
        for (int i2 = tid; i2 < TM * TN / 4; i2 += NTHREADS) {
            const int row = i2 >> 6;
            const int c4  = i2 & 63;
            dst[i2] = *reinterpret_cast<const float4*>(&C[row * CPITCH + c4 * 4]);
        }
    }

    // ---- pair handshake ----
    __syncthreads();
    if (tid == 0) {
        __threadfence();
        atomicAdd(&g_cnt[mtile], 1);
        volatile int* vc = &g_cnt[mtile];
        while (*vc < 2) { }
        int od = atomicAdd(&g_done[mtile], 1);
        if (od == 1) {            // second to arrive resets for next replay
            g_cnt[mtile]  = 0;
            g_done[mtile] = 0;
        }
    }
    __syncthreads();
    __threadfence();

    // ---- combine + 16x bias expand: this CTA writes rows [khalf*64, +64) ----
    const float4* partner = reinterpret_cast<const float4*>(
        g_scratch + (size_t)(mtile * 2 + (1 - khalf)) * (TM * TN));

    const int c4 = tid & 63;            // float4 column 0..63 (covers 256 cols)
    const int rb = tid >> 6;            // 0..3
    const float4* bias4 = reinterpret_cast<const float4*>(bias);
    float4 bv[16];
    #pragma unroll
    for (int r = 0; r < 16; r++)
        bv[r] = bias4[r * 64 + c4];

    #pragma unroll 1
    for (int j = 0; j < 16; j++) {
        const int row = khalf * 64 + rb + j * 4;    // local C row
        float4 v = *reinterpret_cast<const float4*>(&C[row * CPITCH + c4 * 4]);
        const float4 p = __ldcg(&partner[row * 64 + c4]);
        v.x = (v.x + p.x) * TRUNC_FIX;
        v.y = (v.y + p.y) * TRUNC_FIX;
        v.z = (v.z + p.z) * TRUNC_FIX;
        v.w = (v.w + p.w) * TRUNC_FIX;
        float* orow = out + (size_t)(m0 + row) * OUTF + c4 * 4;
        #pragma unroll
        for (int r = 0; r < 16; r++) {
            float4 o;
            o.x = v.x + bv[r].x;
            o.y = v.y + bv[r].y;
            o.z = v.z + bv[r].z;
            o.w = v.w + bv[r].w;
            *reinterpret_cast<float4*>(&orow[r * 256]) = o;
        }
    }
}

// ---------------- host side ----------------
extern "C" void kernel_launch(void* const* d_in, const int* in_sizes, int n_in,
                              void* d_out, int out_size) {
    const float* x    = (const float*)d_in[0];   // [8192, 4096]
    const float* w    = (const float*)d_in[1];   // [256, 4096]
    const float* bias = (const float*)d_in[2];   // [4096]
    float* out        = (float*)d_out;           // [8192, 4096]

    static bool attr_set = false;
    if (!attr_set) {
        cudaFuncSetAttribute(swfc_mma_kernel,
                             cudaFuncAttributeMaxDynamicSharedMemorySize,
                             SMEM_BYTES);
        attr_set = true;
    }

    swfc_mma_kernel<<<BATCH / TM * 2, NTHREADS, SMEM_BYTES>>>(x, w, bias, out);
}